// round 1
// baseline (speedup 1.0000x reference)
#include <cuda_runtime.h>

// ---------------------------------------------------------------------------
// CMIAttentionMatrixForAcrobot: algebraically restructured.
//
//   T[j,i]   = sum_n data_q[n,i] * W_lin[j,n]                (split-K col-red)
//   k[j,m]   = sum_i data_k[j,i] * W_k[m,i] + b_k[m]         (row-GEMV)
//   nq[m,j]  = sum_i W_q[m,i] * T[j,i] + b_q[m]*slin[j] + b_lin[j]
//   kmod[j,m]= relu6(k^2 + 2k + nq*(1+|k|))                  (fused in row-GEMV)
//   v[j,i]   = sum_m W_q[m,i] * kmod[j,m]                    (split-K col-red)
//   c[j]     = sum_m b_q[m] * kmod[j,m]
//   out[n,j] = (sum_i data_q[n,i] * v[j,i] + c[j]) / 64      (row-GEMV)
// ---------------------------------------------------------------------------

#define N_DIM 4096
#define JD 6
#define NSPLIT 64
#define RPS (N_DIM / NSPLIT)   // rows per split = 64

// scratch (static device globals; no allocation)
__device__ float g_Tpart[NSPLIT * JD * N_DIM];
__device__ float g_vpart[NSPLIT * JD * N_DIM];
__device__ float g_T[JD * N_DIM];
__device__ float g_v[JD * N_DIM];
__device__ float g_k[JD * N_DIM];
__device__ float g_kmod[JD * N_DIM];
__device__ float g_slin[JD];
__device__ float g_c[JD];

// --------------------------------------------------------------------------
// slin[j] = sum_n W_lin[j,n]   (one warp per j)
// --------------------------------------------------------------------------
__global__ void init_slin_kernel(const float* __restrict__ Wlin) {
    const int wj = threadIdx.x >> 5;
    const int lane = threadIdx.x & 31;
    if (wj >= JD) return;
    const float4* p = (const float4*)(Wlin + wj * N_DIM);
    float s = 0.0f;
    for (int q = lane; q < N_DIM / 4; q += 32) {
        float4 v = p[q];
        s += v.x + v.y + v.z + v.w;
    }
    #pragma unroll
    for (int o = 16; o; o >>= 1) s += __shfl_xor_sync(0xffffffffu, s, o);
    if (lane == 0) g_slin[wj] = s;
}

// --------------------------------------------------------------------------
// split-K column reduction: part[split][j][i] = sum_{rows in split} big[r,i]*w[j,r]
// which==0: big=data_q, w=W_lin -> g_Tpart
// which==1: big=W_q,    w=g_kmod -> g_vpart
// grid (4, NSPLIT), 256 threads. Each thread owns 4 contiguous columns (float4).
// --------------------------------------------------------------------------
__global__ void splitk_kernel(const float* __restrict__ big,
                              const float* __restrict__ w_in,
                              int which) {
    const float* __restrict__ w = which ? g_kmod : w_in;
    float* __restrict__ part = which ? g_vpart : g_Tpart;

    const int tid = threadIdx.x;
    const int c0 = blockIdx.x * 1024 + tid * 4;
    const int r0 = blockIdx.y * RPS;

    __shared__ float ws[JD][RPS];
    for (int idx = tid; idx < JD * RPS; idx += 256) {
        int j = idx / RPS, rr = idx % RPS;
        ws[j][rr] = w[j * N_DIM + r0 + rr];
    }
    __syncthreads();

    float4 acc[JD];
    #pragma unroll
    for (int j = 0; j < JD; j++) acc[j] = make_float4(0.f, 0.f, 0.f, 0.f);

    const float4* bp = (const float4*)(big + (size_t)r0 * N_DIM) + (c0 >> 2);
    #pragma unroll 4
    for (int rr = 0; rr < RPS; rr++) {
        float4 d = bp[(size_t)rr * (N_DIM / 4)];
        #pragma unroll
        for (int j = 0; j < JD; j++) {
            float wv = ws[j][rr];
            acc[j].x = fmaf(d.x, wv, acc[j].x);
            acc[j].y = fmaf(d.y, wv, acc[j].y);
            acc[j].z = fmaf(d.z, wv, acc[j].z);
            acc[j].w = fmaf(d.w, wv, acc[j].w);
        }
    }

    float* p = part + (size_t)blockIdx.y * (JD * N_DIM);
    #pragma unroll
    for (int j = 0; j < JD; j++)
        *(float4*)(p + j * N_DIM + c0) = acc[j];
}

// --------------------------------------------------------------------------
// reduce partials: out[idx] = sum_s part[s][idx]. 24 blocks x 256 threads.
// --------------------------------------------------------------------------
__global__ void reduce_parts_kernel(int which) {
    const float* __restrict__ part = which ? g_vpart : g_Tpart;
    float* __restrict__ out = which ? g_v : g_T;
    const int idx = blockIdx.x * blockDim.x + threadIdx.x;   // float4 index
    const float4* p4 = (const float4*)part;
    float4 acc = make_float4(0.f, 0.f, 0.f, 0.f);
    #pragma unroll 8
    for (int s = 0; s < NSPLIT; s++) {
        float4 v = p4[(size_t)s * (JD * N_DIM / 4) + idx];
        acc.x += v.x; acc.y += v.y; acc.z += v.z; acc.w += v.w;
    }
    ((float4*)out)[idx] = acc;
}

// --------------------------------------------------------------------------
// row-GEMV: for each row r of big: acc[j] = sum_i big[r,i]*S[j,i]; epilogue by mode.
//   mode 0: S=data_k,  out = g_k[j][r]   = acc + b_k[r]                 (a1=b_k)
//   mode 1: S=g_T,     out = g_kmod[j][r]= relu6(k^2+2k+nq*(1+|k|))     (a1=b_q, a2=b_lin)
//   mode 2: S=g_v,     out[r*6+j] = (acc + c[j]) / 64                   (out_io=d_out)
// 256 threads (8 warps), 4 rows per warp -> 32 rows/block, grid 128.
// --------------------------------------------------------------------------
__global__ void rowgemv_kernel(const float* __restrict__ big,
                               const float* __restrict__ S_in,
                               float* __restrict__ out_io,
                               int mode,
                               const float* __restrict__ a1,
                               const float* __restrict__ a2) {
    const float* __restrict__ S = (mode == 0) ? S_in : ((mode == 1) ? g_T : g_v);

    __shared__ float4 ss[JD][256];   // 6 x 1024 floats per tile = 24KB

    const int tid = threadIdx.x;
    const int wid = tid >> 5;
    const int lane = tid & 31;
    const int r0 = blockIdx.x * 32 + wid * 4;

    float acc[4][JD];
    #pragma unroll
    for (int r = 0; r < 4; r++)
        #pragma unroll
        for (int j = 0; j < JD; j++) acc[r][j] = 0.0f;

    for (int t = 0; t < 4; t++) {
        __syncthreads();
        for (int idx = tid; idx < JD * 256; idx += 256) {
            int j = idx >> 8, q = idx & 255;
            ss[j][q] = ((const float4*)(S + j * N_DIM + t * 1024))[q];
        }
        __syncthreads();

        const float4* b0 = (const float4*)(big + (size_t)(r0 + 0) * N_DIM + t * 1024);
        const float4* b1 = (const float4*)(big + (size_t)(r0 + 1) * N_DIM + t * 1024);
        const float4* b2 = (const float4*)(big + (size_t)(r0 + 2) * N_DIM + t * 1024);
        const float4* b3 = (const float4*)(big + (size_t)(r0 + 3) * N_DIM + t * 1024);

        #pragma unroll 2
        for (int it = 0; it < 8; it++) {
            const int q = it * 32 + lane;
            float4 m0 = b0[q], m1 = b1[q], m2 = b2[q], m3 = b3[q];
            #pragma unroll
            for (int j = 0; j < JD; j++) {
                float4 sv = ss[j][q];
                acc[0][j] = fmaf(m0.x, sv.x, fmaf(m0.y, sv.y, fmaf(m0.z, sv.z, fmaf(m0.w, sv.w, acc[0][j]))));
                acc[1][j] = fmaf(m1.x, sv.x, fmaf(m1.y, sv.y, fmaf(m1.z, sv.z, fmaf(m1.w, sv.w, acc[1][j]))));
                acc[2][j] = fmaf(m2.x, sv.x, fmaf(m2.y, sv.y, fmaf(m2.z, sv.z, fmaf(m2.w, sv.w, acc[2][j]))));
                acc[3][j] = fmaf(m3.x, sv.x, fmaf(m3.y, sv.y, fmaf(m3.z, sv.z, fmaf(m3.w, sv.w, acc[3][j]))));
            }
        }
    }

    #pragma unroll
    for (int r = 0; r < 4; r++)
        #pragma unroll
        for (int j = 0; j < JD; j++)
            #pragma unroll
            for (int o = 16; o; o >>= 1)
                acc[r][j] += __shfl_xor_sync(0xffffffffu, acc[r][j], o);

    if (lane == 0) {
        #pragma unroll
        for (int r = 0; r < 4; r++) {
            const int row = r0 + r;
            if (mode == 0) {
                float b = a1[row];
                #pragma unroll
                for (int j = 0; j < JD; j++)
                    g_k[j * N_DIM + row] = acc[r][j] + b;
            } else if (mode == 1) {
                float bq = a1[row];
                #pragma unroll
                for (int j = 0; j < JD; j++) {
                    float nq = acc[r][j] + bq * g_slin[j] + a2[j];
                    float kv = g_k[j * N_DIM + row];
                    float x = fmaf(kv, kv, 2.0f * kv) + nq * (1.0f + fabsf(kv));
                    g_kmod[j * N_DIM + row] = fminf(fmaxf(x, 0.0f), 6.0f);
                }
            } else {
                #pragma unroll
                for (int j = 0; j < JD; j++)
                    out_io[row * JD + j] = (acc[r][j] + g_c[j]) * 0.015625f;
            }
        }
    }
}

// --------------------------------------------------------------------------
// c[j] = sum_m b_q[m] * g_kmod[j][m]  (one block)
// --------------------------------------------------------------------------
__global__ void compute_c_kernel(const float* __restrict__ bq) {
    __shared__ float red[JD][256];
    const int tid = threadIdx.x;
    float p[JD];
    #pragma unroll
    for (int j = 0; j < JD; j++) p[j] = 0.0f;

    const float4* b4 = (const float4*)bq;
    const float4* k4 = (const float4*)g_kmod;
    for (int q = tid; q < N_DIM / 4; q += 256) {
        float4 b = b4[q];
        #pragma unroll
        for (int j = 0; j < JD; j++) {
            float4 k = k4[j * (N_DIM / 4) + q];
            p[j] += b.x * k.x + b.y * k.y + b.z * k.z + b.w * k.w;
        }
    }
    #pragma unroll
    for (int j = 0; j < JD; j++) red[j][tid] = p[j];
    __syncthreads();
    for (int s = 128; s > 0; s >>= 1) {
        if (tid < s) {
            #pragma unroll
            for (int j = 0; j < JD; j++) red[j][tid] += red[j][tid + s];
        }
        __syncthreads();
    }
    if (tid < JD) g_c[tid] = red[tid][0];
}

// --------------------------------------------------------------------------
extern "C" void kernel_launch(void* const* d_in, const int* in_sizes, int n_in,
                              void* d_out, int out_size) {
    const float* data_q = (const float*)d_in[0];   // [4096,4096]
    const float* data_k = (const float*)d_in[1];   // [6,4096]
    const float* W_q    = (const float*)d_in[2];   // [4096,4096]
    const float* b_q    = (const float*)d_in[3];   // [4096]
    const float* W_lin  = (const float*)d_in[4];   // [6,4096]
    const float* b_lin  = (const float*)d_in[5];   // [6]
    const float* W_k    = (const float*)d_in[6];   // [4096,4096]
    const float* b_k    = (const float*)d_in[7];   // [4096]
    float* out = (float*)d_out;                    // [4096,6]

    init_slin_kernel<<<1, 192>>>(W_lin);
    splitk_kernel<<<dim3(4, NSPLIT), 256>>>(data_q, W_lin, 0);      // T partials
    reduce_parts_kernel<<<24, 256>>>(0);                            // T
    rowgemv_kernel<<<128, 256>>>(W_k, data_k, nullptr, 0, b_k, nullptr);   // k
    rowgemv_kernel<<<128, 256>>>(W_q, nullptr, nullptr, 1, b_q, b_lin);    // kmod
    compute_c_kernel<<<1, 256>>>(b_q);                              // c
    splitk_kernel<<<dim3(4, NSPLIT), 256>>>(W_q, nullptr, 1);       // v partials
    reduce_parts_kernel<<<24, 256>>>(1);                            // v
    rowgemv_kernel<<<128, 256>>>(data_q, nullptr, out, 2, nullptr, nullptr); // dot
}

// round 2
// speedup vs baseline: 1.1565x; 1.1565x over previous
#include <cuda_runtime.h>

// ---------------------------------------------------------------------------
// CMIAttentionMatrixForAcrobot, algebraically restructured (5 HBM-bound passes):
//   T[j,i]   = sum_n data_q[n,i] * W_lin[j,n]                (split-K col-red)
//   k[j,m]   = sum_i data_k[j,i] * W_k[m,i] + b_k[m]         (row-GEMV, k-split)
//   nq[m,j]  = sum_i W_q[m,i] * T[j,i] + b_q[m]*slin[j] + b_lin[j]
//   kmod     = relu6(k^2 + 2k + nq*(1+|k|))                  (epilogue A)
//   v[j,i]   = sum_m W_q[m,i] * kmod[j,m]                    (split-K col-red)
//   c[j]     = sum_m b_q[m] * kmod[j,m]                      (epilogue A partials)
//   out[n,j] = (sum_i data_q[n,i] * v[j,i] + c[j]) / 64      (row-GEMV + epi B)
// ---------------------------------------------------------------------------

#define N_DIM 4096
#define JD 6
#define NSPLIT 128
#define RPS (N_DIM / NSPLIT)     // 32 rows per split
#define KSPLIT 4                 // column splits for row-GEMV
#define CPK (N_DIM / KSPLIT)     // 1024 cols per split
#define EPI_BLOCKS 16

// scratch (static device globals; no allocation)
__device__ float g_Tpart[NSPLIT * JD * N_DIM];
__device__ float g_vpart[NSPLIT * JD * N_DIM];
__device__ float g_T[JD * N_DIM];
__device__ float g_v[JD * N_DIM];
__device__ float g_kmod[JD * N_DIM];
__device__ float g_rgpart[3 * KSPLIT * N_DIM * JD];   // row-GEMV partials, 3 passes
__device__ float g_cpart[EPI_BLOCKS * JD];
__device__ float g_slin[JD];

// --------------------------------------------------------------------------
// slin[j] = sum_n W_lin[j,n]   (one warp per j)
// --------------------------------------------------------------------------
__global__ void init_slin_kernel(const float* __restrict__ Wlin) {
    const int wj = threadIdx.x >> 5;
    const int lane = threadIdx.x & 31;
    if (wj >= JD) return;
    const float4* p = (const float4*)(Wlin + wj * N_DIM);
    float s = 0.0f;
    for (int q = lane; q < N_DIM / 4; q += 32) {
        float4 v = p[q];
        s += v.x + v.y + v.z + v.w;
    }
    #pragma unroll
    for (int o = 16; o; o >>= 1) s += __shfl_xor_sync(0xffffffffu, s, o);
    if (lane == 0) g_slin[wj] = s;
}

// --------------------------------------------------------------------------
// split-K column reduction: part[split][j][i] = sum_{rows in split} big[r,i]*w[j,r]
// which==0: big=data_q, w=W_lin -> g_Tpart ; which==1: big=W_q, w=g_kmod -> g_vpart
// grid (4, NSPLIT=128) = 512 blocks, 256 threads, thread owns 4 contiguous cols.
// --------------------------------------------------------------------------
__global__ void splitk_kernel(const float* __restrict__ big,
                              const float* __restrict__ w_in,
                              int which) {
    const float* __restrict__ w = which ? g_kmod : w_in;
    float* __restrict__ part = which ? g_vpart : g_Tpart;

    const int tid = threadIdx.x;
    const int c0 = blockIdx.x * 1024 + tid * 4;
    const int r0 = blockIdx.y * RPS;

    __shared__ float ws[JD][RPS];
    for (int idx = tid; idx < JD * RPS; idx += 256) {
        int j = idx / RPS, rr = idx % RPS;
        ws[j][rr] = w[j * N_DIM + r0 + rr];
    }
    __syncthreads();

    float4 acc[JD];
    #pragma unroll
    for (int j = 0; j < JD; j++) acc[j] = make_float4(0.f, 0.f, 0.f, 0.f);

    const float4* bp = (const float4*)(big + (size_t)r0 * N_DIM) + (c0 >> 2);
    #pragma unroll 4
    for (int rr = 0; rr < RPS; rr++) {
        float4 d = bp[(size_t)rr * (N_DIM / 4)];
        #pragma unroll
        for (int j = 0; j < JD; j++) {
            float wv = ws[j][rr];
            acc[j].x = fmaf(d.x, wv, acc[j].x);
            acc[j].y = fmaf(d.y, wv, acc[j].y);
            acc[j].z = fmaf(d.z, wv, acc[j].z);
            acc[j].w = fmaf(d.w, wv, acc[j].w);
        }
    }

    float* p = part + (size_t)blockIdx.y * (JD * N_DIM);
    #pragma unroll
    for (int j = 0; j < JD; j++)
        *(float4*)(p + j * N_DIM + c0) = acc[j];
}

// --------------------------------------------------------------------------
// reduce partials: out[idx] = sum_s part[s][idx]. 24 blocks x 256 threads.
// --------------------------------------------------------------------------
__global__ void reduce_parts_kernel(int which) {
    const float* __restrict__ part = which ? g_vpart : g_Tpart;
    float* __restrict__ out = which ? g_v : g_T;
    const int idx = blockIdx.x * blockDim.x + threadIdx.x;   // float4 index
    const float4* p4 = (const float4*)part;
    float4 acc = make_float4(0.f, 0.f, 0.f, 0.f);
    #pragma unroll 8
    for (int s = 0; s < NSPLIT; s++) {
        float4 v = p4[(size_t)s * (JD * N_DIM / 4) + idx];
        acc.x += v.x; acc.y += v.y; acc.z += v.z; acc.w += v.w;
    }
    ((float4*)out)[idx] = acc;
}

// --------------------------------------------------------------------------
// row-GEMV with column split: for rows r: partial[j] = sum_{i in split} big[r,i]*S[j,i]
//   sel 0: S=S_in (data_k);  sel 1: S=g_T;  sel 2: S=g_v
// grid (128, KSPLIT=4) = 512 blocks, 256 threads (8 warps x 4 rows = 32 rows/blk).
// Single 24KB S-tile per block, one sync. Partials -> g_rgpart[sel][ks][row][j].
// --------------------------------------------------------------------------
__global__ void __launch_bounds__(256) rowgemv_kernel(
        const float* __restrict__ big,
        const float* __restrict__ S_in,
        int sel) {
    const float* __restrict__ S = (sel == 0) ? S_in : ((sel == 1) ? g_T : g_v);

    __shared__ float4 ss[JD][CPK / 4];   // 6 x 1024 floats = 24KB

    const int tid = threadIdx.x;
    const int wid = tid >> 5;
    const int lane = tid & 31;
    const int ks = blockIdx.y;
    const int r0 = blockIdx.x * 32 + wid * 4;
    const int cbase = ks * CPK;

    for (int idx = tid; idx < JD * (CPK / 4); idx += 256) {
        int j = idx >> 8, q = idx & 255;
        ss[j][q] = ((const float4*)(S + j * N_DIM + cbase))[q];
    }
    __syncthreads();

    float acc[4][JD];
    #pragma unroll
    for (int r = 0; r < 4; r++)
        #pragma unroll
        for (int j = 0; j < JD; j++) acc[r][j] = 0.0f;

    const float4* b0 = (const float4*)(big + (size_t)(r0 + 0) * N_DIM + cbase);
    const float4* b1 = (const float4*)(big + (size_t)(r0 + 1) * N_DIM + cbase);
    const float4* b2 = (const float4*)(big + (size_t)(r0 + 2) * N_DIM + cbase);
    const float4* b3 = (const float4*)(big + (size_t)(r0 + 3) * N_DIM + cbase);

    #pragma unroll 2
    for (int it = 0; it < CPK / 128; it++) {     // 8 iterations
        const int q = it * 32 + lane;
        float4 m0 = b0[q], m1 = b1[q], m2 = b2[q], m3 = b3[q];
        #pragma unroll
        for (int j = 0; j < JD; j++) {
            float4 sv = ss[j][q];
            acc[0][j] = fmaf(m0.x, sv.x, fmaf(m0.y, sv.y, fmaf(m0.z, sv.z, fmaf(m0.w, sv.w, acc[0][j]))));
            acc[1][j] = fmaf(m1.x, sv.x, fmaf(m1.y, sv.y, fmaf(m1.z, sv.z, fmaf(m1.w, sv.w, acc[1][j]))));
            acc[2][j] = fmaf(m2.x, sv.x, fmaf(m2.y, sv.y, fmaf(m2.z, sv.z, fmaf(m2.w, sv.w, acc[2][j]))));
            acc[3][j] = fmaf(m3.x, sv.x, fmaf(m3.y, sv.y, fmaf(m3.z, sv.z, fmaf(m3.w, sv.w, acc[3][j]))));
        }
    }

    #pragma unroll
    for (int r = 0; r < 4; r++)
        #pragma unroll
        for (int j = 0; j < JD; j++)
            #pragma unroll
            for (int o = 16; o; o >>= 1)
                acc[r][j] += __shfl_xor_sync(0xffffffffu, acc[r][j], o);

    if (lane == 0) {
        float* p = g_rgpart + ((size_t)(sel * KSPLIT + ks) * N_DIM) * JD;
        #pragma unroll
        for (int r = 0; r < 4; r++) {
            const int row = r0 + r;
            #pragma unroll
            for (int j = 0; j < JD; j++)
                p[row * JD + j] = acc[r][j];
        }
    }
}

// --------------------------------------------------------------------------
// Epilogue A: per row m, finish k and nq from partials, produce kmod and the
// per-block c partials (c[j] = sum_m b_q[m]*kmod[j,m]).
// grid EPI_BLOCKS=16 x 256 (one thread per row).
// --------------------------------------------------------------------------
__global__ void epilogueA_kernel(const float* __restrict__ b_k,
                                 const float* __restrict__ b_q,
                                 const float* __restrict__ b_lin) {
    __shared__ float red[JD][256];
    const int tid = threadIdx.x;
    const int m = blockIdx.x * 256 + tid;

    float k[JD], nq[JD];
    #pragma unroll
    for (int j = 0; j < JD; j++) { k[j] = 0.f; nq[j] = 0.f; }

    #pragma unroll
    for (int ks = 0; ks < KSPLIT; ks++) {
        const float* p0 = g_rgpart + ((size_t)(0 * KSPLIT + ks) * N_DIM + m) * JD;
        const float* p1 = g_rgpart + ((size_t)(1 * KSPLIT + ks) * N_DIM + m) * JD;
        #pragma unroll
        for (int j = 0; j < JD; j++) { k[j] += p0[j]; nq[j] += p1[j]; }
    }

    const float bk = b_k[m];
    const float bq = b_q[m];
    float cp[JD];
    #pragma unroll
    for (int j = 0; j < JD; j++) {
        float kv = k[j] + bk;
        float nqv = nq[j] + bq * g_slin[j] + b_lin[j];
        float x = fmaf(kv, kv, 2.0f * kv) + nqv * (1.0f + fabsf(kv));
        float km = fminf(fmaxf(x, 0.0f), 6.0f);
        g_kmod[j * N_DIM + m] = km;
        cp[j] = bq * km;
    }

    #pragma unroll
    for (int j = 0; j < JD; j++) red[j][tid] = cp[j];
    __syncthreads();
    for (int s = 128; s > 0; s >>= 1) {
        if (tid < s) {
            #pragma unroll
            for (int j = 0; j < JD; j++) red[j][tid] += red[j][tid + s];
        }
        __syncthreads();
    }
    if (tid < JD) g_cpart[blockIdx.x * JD + tid] = red[tid][0];
}

// --------------------------------------------------------------------------
// Epilogue B: out[m,j] = (sum_ks part2[ks][m][j] + c[j]) / 64
// c[j] summed inline from the 16 block partials (broadcast reads).
// --------------------------------------------------------------------------
__global__ void epilogueB_kernel(float* __restrict__ out) {
    const int tid = threadIdx.x;
    const int m = blockIdx.x * 256 + tid;

    float c[JD];
    #pragma unroll
    for (int j = 0; j < JD; j++) c[j] = 0.f;
    #pragma unroll
    for (int b = 0; b < EPI_BLOCKS; b++)
        #pragma unroll
        for (int j = 0; j < JD; j++) c[j] += g_cpart[b * JD + j];

    float acc[JD];
    #pragma unroll
    for (int j = 0; j < JD; j++) acc[j] = c[j];
    #pragma unroll
    for (int ks = 0; ks < KSPLIT; ks++) {
        const float* p2 = g_rgpart + ((size_t)(2 * KSPLIT + ks) * N_DIM + m) * JD;
        #pragma unroll
        for (int j = 0; j < JD; j++) acc[j] += p2[j];
    }
    #pragma unroll
    for (int j = 0; j < JD; j++)
        out[m * JD + j] = acc[j] * 0.015625f;
}

// --------------------------------------------------------------------------
extern "C" void kernel_launch(void* const* d_in, const int* in_sizes, int n_in,
                              void* d_out, int out_size) {
    const float* data_q = (const float*)d_in[0];   // [4096,4096]
    const float* data_k = (const float*)d_in[1];   // [6,4096]
    const float* W_q    = (const float*)d_in[2];   // [4096,4096]
    const float* b_q    = (const float*)d_in[3];   // [4096]
    const float* W_lin  = (const float*)d_in[4];   // [6,4096]
    const float* b_lin  = (const float*)d_in[5];   // [6]
    const float* W_k    = (const float*)d_in[6];   // [4096,4096]
    const float* b_k    = (const float*)d_in[7];   // [4096]
    float* out = (float*)d_out;                    // [4096,6]

    init_slin_kernel<<<1, 192>>>(W_lin);
    splitk_kernel<<<dim3(4, NSPLIT), 256>>>(data_q, W_lin, 0);           // T partials
    reduce_parts_kernel<<<24, 256>>>(0);                                 // g_T
    rowgemv_kernel<<<dim3(128, KSPLIT), 256>>>(W_k, data_k, 0);          // k partials
    rowgemv_kernel<<<dim3(128, KSPLIT), 256>>>(W_q, nullptr, 1);         // nq partials
    epilogueA_kernel<<<EPI_BLOCKS, 256>>>(b_k, b_q, b_lin);              // kmod + c parts
    splitk_kernel<<<dim3(4, NSPLIT), 256>>>(W_q, nullptr, 1);            // v partials
    reduce_parts_kernel<<<24, 256>>>(1);                                 // g_v
    rowgemv_kernel<<<dim3(128, KSPLIT), 256>>>(data_q, nullptr, 2);      // dot partials
    epilogueB_kernel<<<EPI_BLOCKS, 256>>>(out);                          // out
}

// round 3
// speedup vs baseline: 1.3650x; 1.1804x over previous
#include <cuda_runtime.h>

// ---------------------------------------------------------------------------
// CMIAttentionMatrixForAcrobot, algebraically restructured (5 HBM passes):
//   T[j,i]   = sum_n data_q[n,i] * W_lin[j,n]                (split-K col-red)
//   k[j,m]   = sum_i data_k[j,i] * W_k[m,i] + b_k[m]         (row-GEMV)
//   nq[m,j]  = sum_i W_q[m,i] * T[j,i] + b_q[m]*slin[j] + b_lin[j]
//   kmod     = relu6(k^2 + 2k + nq*(1+|k|))                  (epilogue A)
//   v[j,i]   = sum_m W_q[m,i] * kmod[j,m]                    (split-K col-red)
//   c[j]     = sum_m b_q[m] * kmod[j,m]                      (epilogue A)
//   out[n,j] = (sum_i data_q[n,i] * v[j,i] + c[j]) / 64      (row-GEMV + epi B)
// Phase 1 merges the two independent 64MB passes (T-splitk + k-rowgemv + slin)
// into one launch for full-chip memory-level parallelism.
// ---------------------------------------------------------------------------

#define N_DIM 4096
#define JD 6
#define NSPLIT 128
#define RPS 32                       // rows per split
#define CSLABS 8                     // 512 cols per splitk block
#define SPLITK_BLOCKS (CSLABS * NSPLIT)   // 1024
#define KSPLIT 8
#define CPK (N_DIM / KSPLIT)         // 512 cols per row-GEMV split
#define RGX (N_DIM / 8)              // 512 row-blocks (8 rows each)
#define RG_BLOCKS (RGX * KSPLIT)     // 4096
#define EPI_BLOCKS 16

// scratch (static device globals; no allocation)
__device__ float g_Tpart[NSPLIT * JD * N_DIM];
__device__ float g_vpart[NSPLIT * JD * N_DIM];
__device__ float g_T[JD * N_DIM];
__device__ float g_v[JD * N_DIM];
__device__ float g_kmod[JD * N_DIM];
__device__ float g_rgpart[3 * KSPLIT * N_DIM * JD];
__device__ float g_cpart[EPI_BLOCKS * JD];
__device__ float g_slin[JD];

// --------------------------------------------------------------------------
// bodies (128-thread blocks)
// --------------------------------------------------------------------------
__device__ __forceinline__ void slin_body(const float* __restrict__ Wlin) {
    const int wid = threadIdx.x >> 5;
    const int lane = threadIdx.x & 31;
    for (int j = wid; j < JD; j += 4) {
        const float4* p = (const float4*)(Wlin + j * N_DIM);
        float s = 0.0f;
        for (int q = lane; q < N_DIM / 4; q += 32) {
            float4 v = p[q];
            s += v.x + v.y + v.z + v.w;
        }
        #pragma unroll
        for (int o = 16; o; o >>= 1) s += __shfl_xor_sync(0xffffffffu, s, o);
        if (lane == 0) g_slin[j] = s;
    }
}

__device__ __forceinline__ void splitk_body(const float* __restrict__ big,
                                            const float* __restrict__ w,
                                            float* __restrict__ part,
                                            int cslab, int split,
                                            float* ws_raw) {
    float (*ws)[RPS] = (float (*)[RPS])ws_raw;
    const int tid = threadIdx.x;
    const int c0 = cslab * 512 + tid * 4;
    const int r0 = split * RPS;

    for (int idx = tid; idx < JD * RPS; idx += 128) {
        int j = idx / RPS, rr = idx % RPS;
        ws[j][rr] = w[j * N_DIM + r0 + rr];
    }
    __syncthreads();

    float4 acc[JD];
    #pragma unroll
    for (int j = 0; j < JD; j++) acc[j] = make_float4(0.f, 0.f, 0.f, 0.f);

    const float4* bp = (const float4*)(big + (size_t)r0 * N_DIM) + (c0 >> 2);
    #pragma unroll 8
    for (int rr = 0; rr < RPS; rr++) {
        float4 d = bp[(size_t)rr * (N_DIM / 4)];
        #pragma unroll
        for (int j = 0; j < JD; j++) {
            float wv = ws[j][rr];
            acc[j].x = fmaf(d.x, wv, acc[j].x);
            acc[j].y = fmaf(d.y, wv, acc[j].y);
            acc[j].z = fmaf(d.z, wv, acc[j].z);
            acc[j].w = fmaf(d.w, wv, acc[j].w);
        }
    }

    float* p = part + (size_t)split * (JD * N_DIM);
    #pragma unroll
    for (int j = 0; j < JD; j++)
        *(float4*)(p + j * N_DIM + c0) = acc[j];
}

__device__ __forceinline__ void rowgemv_body(const float* __restrict__ big,
                                             const float* __restrict__ S,
                                             int sel, int rowblk, int ks,
                                             float4 (*ss)[CPK / 4]) {
    const int tid = threadIdx.x;
    const int wid = tid >> 5;
    const int lane = tid & 31;
    const int cbase = ks * CPK;
    const int r0 = rowblk * 8 + wid * 2;

    for (int idx = tid; idx < JD * (CPK / 4); idx += 128) {
        int j = idx >> 7, q = idx & 127;
        ss[j][q] = ((const float4*)(S + j * N_DIM + cbase))[q];
    }
    __syncthreads();

    float acc0[JD], acc1[JD];
    #pragma unroll
    for (int j = 0; j < JD; j++) { acc0[j] = 0.f; acc1[j] = 0.f; }

    const float4* b0 = (const float4*)(big + (size_t)r0 * N_DIM + cbase);
    const float4* b1 = (const float4*)(big + (size_t)(r0 + 1) * N_DIM + cbase);

    #pragma unroll
    for (int it = 0; it < CPK / 128; it++) {         // 4 iters, fully unrolled
        const int q = it * 32 + lane;
        float4 m0 = b0[q], m1 = b1[q];
        #pragma unroll
        for (int j = 0; j < JD; j++) {
            float4 sv = ss[j][q];
            acc0[j] = fmaf(m0.x, sv.x, fmaf(m0.y, sv.y, fmaf(m0.z, sv.z, fmaf(m0.w, sv.w, acc0[j]))));
            acc1[j] = fmaf(m1.x, sv.x, fmaf(m1.y, sv.y, fmaf(m1.z, sv.z, fmaf(m1.w, sv.w, acc1[j]))));
        }
    }

    #pragma unroll
    for (int j = 0; j < JD; j++) {
        #pragma unroll
        for (int o = 16; o; o >>= 1) {
            acc0[j] += __shfl_xor_sync(0xffffffffu, acc0[j], o);
            acc1[j] += __shfl_xor_sync(0xffffffffu, acc1[j], o);
        }
    }

    if (lane == 0) {
        float* p = g_rgpart + ((size_t)(sel * KSPLIT + ks) * N_DIM) * JD;
        #pragma unroll
        for (int j = 0; j < JD; j++) {
            p[(size_t)r0 * JD + j] = acc0[j];
            p[(size_t)(r0 + 1) * JD + j] = acc1[j];
        }
    }
}

// --------------------------------------------------------------------------
// Phase 1: T-splitk + k-rowgemv + slin, merged (all independent).
// --------------------------------------------------------------------------
__global__ void __launch_bounds__(128) phase1_kernel(
        const float* __restrict__ data_q, const float* __restrict__ W_lin,
        const float* __restrict__ W_k,    const float* __restrict__ data_k) {
    __shared__ float4 ss[JD][CPK / 4];   // 12KB; aliased by splitk's ws
    const int bid = blockIdx.x;
    if (bid < SPLITK_BLOCKS) {
        splitk_body(data_q, W_lin, g_Tpart, bid >> 7, bid & 127, (float*)ss);
    } else if (bid < SPLITK_BLOCKS + RG_BLOCKS) {
        const int rb = bid - SPLITK_BLOCKS;
        rowgemv_body(W_k, data_k, 0, rb >> 3, rb & 7, ss);
    } else {
        slin_body(W_lin);
    }
}

// standalone wrappers
__global__ void __launch_bounds__(128) splitk_kernel(
        const float* __restrict__ big, int which) {
    __shared__ float ws[JD][RPS];
    splitk_body(big, which ? g_kmod : nullptr, which ? g_vpart : g_Tpart,
                blockIdx.x, blockIdx.y, (float*)ws);
}

__global__ void __launch_bounds__(128) rowgemv_kernel(
        const float* __restrict__ big, int sel) {
    __shared__ float4 ss[JD][CPK / 4];
    rowgemv_body(big, (sel == 1) ? g_T : g_v, sel, blockIdx.x, blockIdx.y, ss);
}

// --------------------------------------------------------------------------
// reduce partials: out[idx] = sum_s part[s][idx]. 48 blocks x 128 threads.
// --------------------------------------------------------------------------
__global__ void __launch_bounds__(128) reduce_parts_kernel(int which) {
    const float* __restrict__ part = which ? g_vpart : g_Tpart;
    float* __restrict__ out = which ? g_v : g_T;
    const int idx = blockIdx.x * 128 + threadIdx.x;   // float4 index, 6144 total
    const float4* p4 = (const float4*)part;
    float4 acc = make_float4(0.f, 0.f, 0.f, 0.f);
    #pragma unroll 8
    for (int s = 0; s < NSPLIT; s++) {
        float4 v = p4[(size_t)s * (JD * N_DIM / 4) + idx];
        acc.x += v.x; acc.y += v.y; acc.z += v.z; acc.w += v.w;
    }
    ((float4*)out)[idx] = acc;
}

// --------------------------------------------------------------------------
// Epilogue A: finish k and nq from partials, compute kmod and c partials.
// --------------------------------------------------------------------------
__global__ void __launch_bounds__(256) epilogueA_kernel(
        const float* __restrict__ b_k, const float* __restrict__ b_q,
        const float* __restrict__ b_lin) {
    __shared__ float red[JD][256];
    const int tid = threadIdx.x;
    const int m = blockIdx.x * 256 + tid;

    float k[JD], nq[JD];
    #pragma unroll
    for (int j = 0; j < JD; j++) { k[j] = 0.f; nq[j] = 0.f; }

    #pragma unroll
    for (int ks = 0; ks < KSPLIT; ks++) {
        const float* p0 = g_rgpart + ((size_t)(0 * KSPLIT + ks) * N_DIM + m) * JD;
        const float* p1 = g_rgpart + ((size_t)(1 * KSPLIT + ks) * N_DIM + m) * JD;
        #pragma unroll
        for (int j = 0; j < JD; j++) { k[j] += p0[j]; nq[j] += p1[j]; }
    }

    const float bk = b_k[m];
    const float bq = b_q[m];
    float cp[JD];
    #pragma unroll
    for (int j = 0; j < JD; j++) {
        float kv = k[j] + bk;
        float nqv = nq[j] + bq * g_slin[j] + b_lin[j];
        float x = fmaf(kv, kv, 2.0f * kv) + nqv * (1.0f + fabsf(kv));
        float km = fminf(fmaxf(x, 0.0f), 6.0f);
        g_kmod[j * N_DIM + m] = km;
        cp[j] = bq * km;
    }

    #pragma unroll
    for (int j = 0; j < JD; j++) red[j][tid] = cp[j];
    __syncthreads();
    for (int s = 128; s > 0; s >>= 1) {
        if (tid < s) {
            #pragma unroll
            for (int j = 0; j < JD; j++) red[j][tid] += red[j][tid + s];
        }
        __syncthreads();
    }
    if (tid < JD) g_cpart[blockIdx.x * JD + tid] = red[tid][0];
}

// --------------------------------------------------------------------------
// Epilogue B: out[m,j] = (sum_ks part2[ks][m][j] + c[j]) / 64
// --------------------------------------------------------------------------
__global__ void __launch_bounds__(256) epilogueB_kernel(float* __restrict__ out) {
    const int tid = threadIdx.x;
    const int m = blockIdx.x * 256 + tid;

    float acc[JD];
    #pragma unroll
    for (int j = 0; j < JD; j++) acc[j] = 0.f;
    #pragma unroll
    for (int b = 0; b < EPI_BLOCKS; b++)
        #pragma unroll
        for (int j = 0; j < JD; j++) acc[j] += g_cpart[b * JD + j];

    #pragma unroll
    for (int ks = 0; ks < KSPLIT; ks++) {
        const float* p2 = g_rgpart + ((size_t)(2 * KSPLIT + ks) * N_DIM + m) * JD;
        #pragma unroll
        for (int j = 0; j < JD; j++) acc[j] += p2[j];
    }
    #pragma unroll
    for (int j = 0; j < JD; j++)
        out[m * JD + j] = acc[j] * 0.015625f;
}

// --------------------------------------------------------------------------
extern "C" void kernel_launch(void* const* d_in, const int* in_sizes, int n_in,
                              void* d_out, int out_size) {
    const float* data_q = (const float*)d_in[0];   // [4096,4096]
    const float* data_k = (const float*)d_in[1];   // [6,4096]
    const float* W_q    = (const float*)d_in[2];   // [4096,4096]
    const float* b_q    = (const float*)d_in[3];   // [4096]
    const float* W_lin  = (const float*)d_in[4];   // [6,4096]
    const float* b_lin  = (const float*)d_in[5];   // [6]
    const float* W_k    = (const float*)d_in[6];   // [4096,4096]
    const float* b_k    = (const float*)d_in[7];   // [4096]
    float* out = (float*)d_out;                    // [4096,6]

    // phase 1: T partials + k partials + slin (independent, one launch)
    phase1_kernel<<<SPLITK_BLOCKS + RG_BLOCKS + 1, 128>>>(data_q, W_lin, W_k, data_k);
    reduce_parts_kernel<<<48, 128>>>(0);                              // g_T
    rowgemv_kernel<<<dim3(RGX, KSPLIT), 128>>>(W_q, 1);               // nq partials
    epilogueA_kernel<<<EPI_BLOCKS, 256>>>(b_k, b_q, b_lin);           // kmod + c
    splitk_kernel<<<dim3(CSLABS, NSPLIT), 128>>>(W_q, 1);             // v partials
    reduce_parts_kernel<<<48, 128>>>(1);                              // g_v
    rowgemv_kernel<<<dim3(RGX, KSPLIT), 128>>>(data_q, 2);            // dot partials
    epilogueB_kernel<<<EPI_BLOCKS, 256>>>(out);                       // out
}